// round 9
// baseline (speedup 1.0000x reference)
#include <cuda_runtime.h>
#include <cuda_bf16.h>
#include <cstdint>

// ShapeConv via warp-level mma.sync bf16 m16n8k16 implicit GEMM.
// Round-9: ldmatrix.x4 A-fragment loads (4x fewer LDS issue slots) and
// register-resident cross-tile running max (no per-tile smem reduce/sync).

#define BB 32
#define CC 3
#define LL 8192
#define OO 128
#define KW 64
#define WW (LL - KW + 1)   /* 8129 valid windows */
#define NTILE 128
#define KRED 192
#define APW 100            /* A pitch in 32-bit words (96 data + 4 pad) */
#define NBLK 296           /* 2 CTAs per SM, one wave */
#define NTPB 7             /* tile slots per block; 296*7 >= 2048 */
#define TILES_TOTAL (BB * 64)   /* 2048 */

#define A_OFF    0u        /* 128*APW bf16x2 words = 51200 B */
#define XS32_OFF 51200u    /* 3*192 f32 */
#define SQ_OFF   53504u    /* 192 f32 */
#define S_OFF    54272u    /* 160 f32 half-window sums */
#define XE_OFF   54928u    /* 3*96 bf16x2 */
#define XO_OFF   56080u    /* 3*96 bf16x2 */
#define WS_OFF   57232u    /* 128 f32: 0.5*||w_o||^2 */
#define SMEM_BYTES 57744

__device__ unsigned int g_max[BB * OO];   // monotone-mapped maxima (zero-init)
__device__ unsigned int g_counter;        // ticket (zero-init)

__device__ __forceinline__ unsigned int f2mono(float f) {
    unsigned int u = __float_as_uint(f);
    return (u & 0x80000000u) ? ~u : (u | 0x80000000u);
}
__device__ __forceinline__ float mono2f(unsigned int m) {
    unsigned int u = (m & 0x80000000u) ? (m & 0x7fffffffu) : ~m;
    return __uint_as_float(u);
}
__device__ __forceinline__ uint32_t pack_bf2(float lo, float hi) {
    __nv_bfloat162 h = __float22bfloat162_rn(make_float2(lo, hi));
    return *(uint32_t*)&h;
}
__device__ __forceinline__ void mma_bf16(float* d, const uint32_t* a,
                                         uint32_t b0, uint32_t b1) {
    asm volatile(
        "mma.sync.aligned.m16n8k16.row.col.f32.bf16.bf16.f32 "
        "{%0,%1,%2,%3}, {%4,%5,%6,%7}, {%8,%9}, {%0,%1,%2,%3};"
        : "+f"(d[0]), "+f"(d[1]), "+f"(d[2]), "+f"(d[3])
        : "r"(a[0]), "r"(a[1]), "r"(a[2]), "r"(a[3]), "r"(b0), "r"(b1));
}
__device__ __forceinline__ void ldsm_x4(uint32_t* a, uint32_t saddr) {
    asm volatile(
        "ldmatrix.sync.aligned.m8n8.x4.shared.b16 {%0,%1,%2,%3}, [%4];"
        : "=r"(a[0]), "=r"(a[1]), "=r"(a[2]), "=r"(a[3]) : "r"(saddr));
}

extern "C" __global__ void __launch_bounds__(256, 2)
shapeconv_fused(const float* __restrict__ xg, const float* __restrict__ wg,
                float* __restrict__ out) {
    extern __shared__ char smem[];
    uint32_t* A_s  = (uint32_t*)(smem + A_OFF);     // [128][APW] bf16x2
    float*    xs32 = (float*)(smem + XS32_OFF);     // [3][192]
    float*    sq   = (float*)(smem + SQ_OFF);       // [192]
    float*    S_s  = (float*)(smem + S_OFF);        // [160]
    uint32_t* xe   = (uint32_t*)(smem + XE_OFF);    // [3][96]
    uint32_t* xo   = (uint32_t*)(smem + XO_OFF);    // [3][96]
    float*    ws   = (float*)(smem + WS_OFF);       // [128]

    const int tid  = threadIdx.x;
    const int wid  = tid >> 5;
    const int lane = tid & 31;
    const int blk  = blockIdx.x;

    const int m0  = (wid & 3) * 32;    // warp o-base
    const int n0w = (wid >> 2) * 64;   // warp t-base
    const int r4  = lane >> 2;
    const int q4  = lane & 3;

    // ---- A staging: warp w owns o-rows [16w,16w+16); coalesced float2 loads,
    // conflict-free STS, shuffle-reduced squared norm -> ws[o]. ----
    {
        const int o0w = wid * 16;
        #pragma unroll 4
        for (int oi = 0; oi < 16; ++oi) {
            const int o = o0w + oi;
            const float2* wp = (const float2*)(wg + o * KRED);
            float2 v0 = wp[lane], v1 = wp[lane + 32], v2 = wp[lane + 64];
            uint32_t* ap = A_s + o * APW;
            ap[lane]      = pack_bf2(v0.x, v0.y);
            ap[lane + 32] = pack_bf2(v1.x, v1.y);
            ap[lane + 64] = pack_bf2(v2.x, v2.y);
            float s = v0.x * v0.x + v0.y * v0.y + v1.x * v1.x + v1.y * v1.y
                    + v2.x * v2.x + v2.y * v2.y;
            #pragma unroll
            for (int d = 16; d; d >>= 1)
                s += __shfl_xor_sync(0xffffffffu, s, d);
            if (lane == 0) ws[o] = 0.5f * s;
        }
    }

    // B-frag addressing: s = n0w + 8u + r4 + 2*q4 (+c*64); parity(s) = r4&1
    const uint32_t* xpar = (r4 & 1) ? xo : xe;
    const int wbase = (n0w + r4 + 2 * q4) >> 1;

    // ldmatrix A addressing: lane -> row = m0 + (lane&15), col-half (lane>>4)*4 words
    const uint32_t Abase = (uint32_t)__cvta_generic_to_shared(A_s);
    const uint32_t addrA0 =
        Abase + ((((m0 + (lane & 15)) * APW) + ((lane >> 4) << 2)) << 2);
    const uint32_t addrA1 = addrA0 + (16 * APW << 2);

    // ---- flat tile schedule: tile tl -> (b = tl>>6, t0 = (tl&63)*128) ----
    int tl = blk * NTPB;

    // prefetch first tile's x slice (thread tid<192 owns position tid)
    float p0 = 0.f, p1 = 0.f, p2 = 0.f;
    if (tl < TILES_TOTAL && tid < KRED) {
        const float* xp = xg + (tl >> 6) * CC * LL;
        int g = ((tl & 63) << 7) + tid;
        if (g < LL) { p0 = xp[g]; p1 = xp[LL + g]; p2 = xp[2 * LL + g]; }
    }
    __syncthreads();

    int   cur_b = -1;
    float mrow[4];                         // cross-tile running max (register)
    #pragma unroll
    for (int r = 0; r < 4; ++r) mrow[r] = __int_as_float(0xff800000);

    #pragma unroll 1
    for (int i = 0; i < NTPB; ++i, ++tl) {
        if (tl >= TILES_TOTAL) break;
        const int tb = tl >> 6;
        const int t0 = (tl & 63) << 7;

        if (tb != cur_b) {                 // batch boundary: flush running max
            if (cur_b >= 0) {
                #pragma unroll
                for (int r = 0; r < 4; ++r) {
                    mrow[r] = fmaxf(mrow[r], __shfl_xor_sync(0xffffffffu, mrow[r], 1));
                    mrow[r] = fmaxf(mrow[r], __shfl_xor_sync(0xffffffffu, mrow[r], 2));
                }
                if (q4 == 0) {
                    #pragma unroll
                    for (int r = 0; r < 4; ++r) {
                        int row = m0 + (r >> 1) * 16 + (r & 1) * 8 + r4;
                        atomicMax(&g_max[cur_b * OO + row], f2mono(mrow[r]));
                    }
                }
                #pragma unroll
                for (int r = 0; r < 4; ++r) mrow[r] = __int_as_float(0xff800000);
            }
            cur_b = tb;
        }

        // ---- phase A: spill prefetched regs to smem + squared sums ----
        if (tid < KRED) {
            xs32[tid] = p0; xs32[192 + tid] = p1; xs32[384 + tid] = p2;
            sq[tid] = p0 * p0 + p1 * p1 + p2 * p2;
        }
        __syncthreads();

        // ---- phase B: pack bf16 unfold sources + half-window sums ----
        for (int u = tid; u < CC * 96; u += 256) {
            int c = u / 96, j = u % 96;
            const float* xc = xs32 + c * 192;
            float v0 = xc[2 * j], v1 = xc[2 * j + 1];
            float v2 = (2 * j + 2 < 192) ? xc[2 * j + 2] : 0.f;
            xe[u] = pack_bf2(v0, v1);
            xo[u] = pack_bf2(v1, v2);
        }
        if (tid < 160) {
            float s = 0.f;
            #pragma unroll 8
            for (int k = 0; k < 32; ++k) s += sq[tid + k];
            S_s[tid] = s;
        }
        __syncthreads();

        // ---- prefetch next tile (latency hidden behind MMA) ----
        p0 = p1 = p2 = 0.f;
        if (i + 1 < NTPB && tl + 1 < TILES_TOTAL && tid < KRED) {
            const float* xp = xg + ((tl + 1) >> 6) * CC * LL;
            int g = (((tl + 1) & 63) << 7) + tid;
            if (g < LL) { p0 = xp[g]; p1 = xp[LL + g]; p2 = xp[2 * LL + g]; }
        }

        // ---- MMA mainloop: 32 o x 64 t per warp, K=192; ldmatrix A frags ----
        float acc[2][8][4];
        #pragma unroll
        for (int mi = 0; mi < 2; ++mi)
            #pragma unroll
            for (int nf = 0; nf < 8; ++nf)
                #pragma unroll
                for (int r = 0; r < 4; ++r) acc[mi][nf][r] = 0.f;

        #pragma unroll
        for (int c = 0; c < CC; ++c) {
            const uint32_t* xp = xpar + c * 96 + wbase;
            uint32_t bb[15];
            #pragma unroll
            for (int u = 0; u < 15; ++u) bb[u] = xp[4 * u];

            #pragma unroll
            for (int j = 0; j < 4; ++j) {
                const uint32_t cb = (uint32_t)(c * 32 + j * 8) << 2;
                uint32_t a[2][4];
                ldsm_x4(a[0], addrA0 + cb);
                ldsm_x4(a[1], addrA1 + cb);
                #pragma unroll
                for (int nf = 0; nf < 8; ++nf) {
                    uint32_t b0 = bb[2 * j + nf], b1 = bb[2 * j + nf + 1];
                    mma_bf16(acc[0][nf], a[0], b0, b1);
                    mma_bf16(acc[1][nf], a[1], b0, b1);
                }
            }
        }

        // ---- epilogue: fold (D - win) into register-resident running max ----
        #pragma unroll
        for (int mi = 0; mi < 2; ++mi)
            #pragma unroll
            for (int nf = 0; nf < 8; ++nf) {
                int ncol = n0w + nf * 8 + 2 * q4;
                float w0 = 0.5f * (S_s[ncol] + S_s[ncol + 32]);
                float w1 = 0.5f * (S_s[ncol + 1] + S_s[ncol + 33]);
                if (t0 + ncol >= WW)     w0 = __int_as_float(0x7f800000);
                if (t0 + ncol + 1 >= WW) w1 = __int_as_float(0x7f800000);
                float* d = acc[mi][nf];
                mrow[mi * 2]     = fmaxf(mrow[mi * 2],
                                         fmaxf(d[0] - w0, d[1] - w1));
                mrow[mi * 2 + 1] = fmaxf(mrow[mi * 2 + 1],
                                         fmaxf(d[2] - w0, d[3] - w1));
            }
        // no sync here: xe/xo/S_s are only rewritten after the next phase-A sync
    }

    if (cur_b >= 0) {                      // final flush
        #pragma unroll
        for (int r = 0; r < 4; ++r) {
            mrow[r] = fmaxf(mrow[r], __shfl_xor_sync(0xffffffffu, mrow[r], 1));
            mrow[r] = fmaxf(mrow[r], __shfl_xor_sync(0xffffffffu, mrow[r], 2));
        }
        if (q4 == 0) {
            #pragma unroll
            for (int r = 0; r < 4; ++r) {
                int row = m0 + (r >> 1) * 16 + (r & 1) * 8 + r4;
                atomicMax(&g_max[cur_b * OO + row], f2mono(mrow[r]));
            }
        }
    }

    // ---- last-block inline finalize ----
    __threadfence();
    __shared__ unsigned int s_last;
    if (tid == 0)
        s_last = (atomicAdd(&g_counter, 1u) == NBLK - 1u) ? 1u : 0u;
    __syncthreads();
    if (s_last) {
        for (int idx = tid; idx < BB * OO; idx += 256) {
            int o = idx & (OO - 1);
            float v = mono2f(g_max[idx]);
            out[idx] = -2.0f * (v - ws[o]);
            g_max[idx] = 0u;               // reset for next graph replay
        }
        if (tid == 0) g_counter = 0u;
    }
}

extern "C" void kernel_launch(void* const* d_in, const int* in_sizes, int n_in,
                              void* d_out, int out_size) {
    const float* x = (const float*)d_in[0];
    const float* w = (const float*)d_in[1];
    float* out = (float*)d_out;

    cudaFuncSetAttribute(shapeconv_fused,
                         cudaFuncAttributeMaxDynamicSharedMemorySize, SMEM_BYTES);
    shapeconv_fused<<<NBLK, 256, SMEM_BYTES>>>(x, w, out);
}